// round 1
// baseline (speedup 1.0000x reference)
#include <cuda_runtime.h>

#define F_FACES 65536
#define N_ROWS  131072
#define C_CH    128
#define WDIM    512
#define KNB     9
#define KTOT    1152      // 9*128
#define BM      128
#define BN      128
#define BK      32
#define BMP     132       // padded M stride for transposed A tile

// ---------------- device scratch (no allocations allowed) ----------------
__device__ int   g_flags[2];              // [0]=neigh is int64, [1]=pad byte stride (1 or 4)
__device__ float g_styles[256];           // [b*128+i]
__device__ float g_styles2[256];          // [b*128+i], includes *1/sqrt(128)
__device__ float g_demod[256];            // [b*128+o]
__device__ float g_w2f[768];              // [b][o][i]
__device__ float g_Bmat[2 * KTOT * C_CH]; // [b][k*128+i][o]  modulated+demodulated weight1

// ---------------- packed f32x2 helpers (sm_103a FFMA2) ----------------
typedef unsigned long long f32x2_t;

__device__ __forceinline__ f32x2_t ffma2(f32x2_t a, f32x2_t b, f32x2_t c) {
    f32x2_t d;
    asm("fma.rn.f32x2 %0, %1, %2, %3;" : "=l"(d) : "l"(a), "l"(b), "l"(c));
    return d;
}
__device__ __forceinline__ f32x2_t splat2(float x) {
    f32x2_t d;
    unsigned int xi = __float_as_uint(x);
    asm("mov.b64 %0, {%1, %1};" : "=l"(d) : "r"(xi));
    return d;
}
__device__ __forceinline__ void unpack2(f32x2_t v, float& lo, float& hi) {
    unsigned int a, b;
    asm("mov.b64 {%0, %1}, %2;" : "=r"(a), "=r"(b) : "l"(v));
    lo = __uint_as_float(a);
    hi = __uint_as_float(b);
}

// ---------------- probe: detect int64 neigh / int32 is_pad layouts ----------------
__global__ void probe_kernel(const int* __restrict__ nbr,
                             const unsigned char* __restrict__ padb) {
    __shared__ int s_or[2];
    int t = threadIdx.x;
    if (t < 2) s_or[t] = 0;
    __syncthreads();
    int v = 0;
    if (t < 128) {
        // if neigh is int64, every odd 32-bit word (high word) is 0
        for (int q = 0; q < 32; q++) {
            int j = t * 32 + q;                 // j in [0,4096) < element count
            v |= nbr[2 * j + 1];
        }
        atomicOr(&s_or[0], v);
    } else {
        // if is_pad is int32, every byte with idx%4!=0 is 0
        int tt = t - 128;
        for (int q = 0; q < 32; q++) {
            int idx = tt * 32 + q;              // [0,4096) bytes
            if (idx & 3) v |= (int)padb[idx];
        }
        atomicOr(&s_or[1], v);
    }
    __syncthreads();
    if (t == 0) {
        g_flags[0] = (s_or[0] == 0) ? 1 : 0;
        g_flags[1] = (s_or[1] == 0) ? 4 : 1;
    }
}

// ---------------- styles: 256 blocks, one (b,i) each ----------------
__global__ void styles_kernel(const float* __restrict__ ws,
                              const float* __restrict__ A1, const float* __restrict__ b1,
                              const float* __restrict__ A2, const float* __restrict__ b2) {
    int j = blockIdx.x;
    int b = j >> 7, i = j & 127;
    int t = threadIdx.x;
    const float* w0 = ws + b * 2 * WDIM;
    const float* w1 = w0 + WDIM;
    const float* r1 = A1 + i * WDIM;
    const float* r2 = A2 + i * WDIM;
    float a1 = 0.f, a2 = 0.f;
    for (int jj = t; jj < WDIM; jj += 128) {
        a1 += w0[jj] * r1[jj];
        a2 += w1[jj] * r2[jj];
    }
    __shared__ float s1[128], s2[128];
    s1[t] = a1; s2[t] = a2;
    __syncthreads();
    for (int s = 64; s > 0; s >>= 1) {
        if (t < s) { s1[t] += s1[t + s]; s2[t] += s2[t + s]; }
        __syncthreads();
    }
    if (t == 0) {
        const float RSQ512 = 0.04419417382415922f;  // 1/sqrt(512)
        const float RSQ128 = 0.08838834764831845f;  // 1/sqrt(128)
        g_styles[j]  = s1[0] * RSQ512 + b1[i];
        g_styles2[j] = (s2[0] * RSQ512 + b2[i]) * RSQ128;
    }
}

// ---------------- demod: 256 blocks, one (b,o) each ----------------
__global__ void demod_kernel(const float* __restrict__ w1) {
    int j = blockIdx.x;
    int b = j >> 7, o = j & 127;
    int i = threadIdx.x;
    float s = g_styles[b * 128 + i];
    const float* wp = w1 + o * KTOT + i * KNB;
    float sum = 0.f;
#pragma unroll
    for (int k = 0; k < 9; k++) { float w = wp[k] * s; sum += w * w; }
    __shared__ float sr[128];
    sr[i] = sum;
    __syncthreads();
    for (int st = 64; st > 0; st >>= 1) {
        if (i < st) sr[i] += sr[i + st];
        __syncthreads();
    }
    if (i == 0) g_demod[j] = rsqrtf(sr[0] + 1e-8f);
}

// ---------------- build Bmat [b][k*128+i][o] and w2f ----------------
__global__ void bmat_kernel(const float* __restrict__ w1, const float* __restrict__ w2) {
    int tid = blockIdx.x * blockDim.x + threadIdx.x;
    const int tot = 2 * KTOT * C_CH;
    for (int e = tid; e < tot; e += gridDim.x * blockDim.x) {
        int b  = e / (KTOT * C_CH);
        int r  = e - b * (KTOT * C_CH);
        int kk = r >> 7;          // k*128+i
        int o  = r & 127;
        int k  = kk >> 7;
        int i  = kk & 127;
        g_Bmat[e] = w1[o * KTOT + i * KNB + k] * g_styles[b * 128 + i] * g_demod[b * 128 + o];
    }
    if (tid < 768) {
        int b = tid / 384;
        int r = tid - b * 384;
        int o = r >> 7;
        int i = r & 127;
        g_w2f[tid] = w2[o * 128 + i] * g_styles2[b * 128 + i];
    }
}

// ---------------- main modulated face conv as gathered GEMM ----------------
__global__ void __launch_bounds__(256, 2)
gemm_kernel(const int* __restrict__ nbr,
            const unsigned char* __restrict__ padb,
            const float* __restrict__ cst,
            const float* __restrict__ noise_const,
            const float* __restrict__ noise_strength,
            const float* __restrict__ bias1,
            float* __restrict__ outx)
{
    __shared__ int s_f[BM * KNB];
    __shared__ __align__(16) float s_A[BK * BMP];
    __shared__ __align__(16) float s_B[BK * BN];

    int t = threadIdx.x;
    int row0 = blockIdx.x * BM;
    int b = row0 >> 16;
    int i64 = g_flags[0];
    int pstride = g_flags[1];

    // effective gather index per (row, neighbor); -1 = zero row
    for (int e = t; e < BM * KNB; e += 256) {
        int m = e / 9, k = e - m * 9;
        int gi = (row0 + m) * 9 + k;
        int raw = i64 ? nbr[2 * gi] : nbr[gi];
        unsigned char pb = padb[gi * pstride];
        s_f[e] = (pb == 0 && (unsigned)raw < (unsigned)N_ROWS) ? (raw & (F_FACES - 1)) : -1;
    }
    __syncthreads();

    int tx = t & 15, ty = t >> 4;
    f32x2_t acc[8][4];
#pragma unroll
    for (int i = 0; i < 8; i++)
#pragma unroll
        for (int j = 0; j < 4; j++) acc[i][j] = 0ull;

    const float* Bb = g_Bmat + b * KTOT * C_CH;

    for (int ck = 0; ck < 36; ck++) {
        int k  = ck >> 2;
        int i0 = (ck & 3) << 5;
        // A tile: gather from const (L2-resident), store transposed [BK][BM]
#pragma unroll
        for (int q = 0; q < 4; q++) {
            int v  = t + 256 * q;
            int r  = v >> 3;
            int c4 = v & 7;
            int f  = s_f[r * 9 + k];
            float4 av = make_float4(0.f, 0.f, 0.f, 0.f);
            if (f >= 0) av = *(const float4*)(cst + ((size_t)f * 128 + i0 + c4 * 4));
            int kk0 = c4 * 4;
            s_A[(kk0 + 0) * BMP + r] = av.x;
            s_A[(kk0 + 1) * BMP + r] = av.y;
            s_A[(kk0 + 2) * BMP + r] = av.z;
            s_A[(kk0 + 3) * BMP + r] = av.w;
        }
        // B tile: coalesced
#pragma unroll
        for (int q = 0; q < 4; q++) {
            int v  = t + 256 * q;
            int kk = v >> 5;
            int c  = (v & 31) << 2;
            *(float4*)&s_B[kk * BN + c] = *(const float4*)(Bb + (ck * BK + kk) * C_CH + c);
        }
        __syncthreads();
#pragma unroll
        for (int kk = 0; kk < BK; kk++) {
            float4 a0 = *(const float4*)&s_A[kk * BMP + ty * 8];
            float4 a1 = *(const float4*)&s_A[kk * BMP + ty * 8 + 4];
            f32x2_t b0 = *(const f32x2_t*)&s_B[kk * BN + tx * 8];
            f32x2_t b1 = *(const f32x2_t*)&s_B[kk * BN + tx * 8 + 2];
            f32x2_t b2 = *(const f32x2_t*)&s_B[kk * BN + tx * 8 + 4];
            f32x2_t b3 = *(const f32x2_t*)&s_B[kk * BN + tx * 8 + 6];
            float af[8] = {a0.x, a0.y, a0.z, a0.w, a1.x, a1.y, a1.z, a1.w};
            f32x2_t bf[4] = {b0, b1, b2, b3};
#pragma unroll
            for (int i = 0; i < 8; i++) {
                f32x2_t a2 = splat2(af[i]);
#pragma unroll
                for (int j = 0; j < 4; j++) acc[i][j] = ffma2(a2, bf[j], acc[i][j]);
            }
        }
        __syncthreads();
    }

    // fused epilogue: + noise + bias1, leaky_relu(0.2), * sqrt(2), clip +-256
    float nstr = noise_strength[0];
    float bc[8];
#pragma unroll
    for (int jj = 0; jj < 8; jj++) bc[jj] = bias1[tx * 8 + jj];
    const float GAIN = 1.41421356237f;
#pragma unroll
    for (int i = 0; i < 8; i++) {
        int row = row0 + ty * 8 + i;
        float nz = noise_const[row & (F_FACES - 1)] * nstr;
        float vals[8];
#pragma unroll
        for (int j = 0; j < 4; j++) unpack2(acc[i][j], vals[2 * j], vals[2 * j + 1]);
#pragma unroll
        for (int jj = 0; jj < 8; jj++) {
            float v = vals[jj] + nz + bc[jj];
            v = (v >= 0.f) ? v : 0.2f * v;
            v *= GAIN;
            vals[jj] = fminf(fmaxf(v, -256.f), 256.f);
        }
        float* op = outx + (size_t)row * 128 + tx * 8;
        *(float4*)op       = make_float4(vals[0], vals[1], vals[2], vals[3]);
        *(float4*)(op + 4) = make_float4(vals[4], vals[5], vals[6], vals[7]);
    }
}

// ---------------- second conv (128 -> 3) + bias + clip, warp per row ----------------
__global__ void img_kernel(const int* __restrict__ nbr,
                           const unsigned char* __restrict__ padb,
                           const float* __restrict__ x,
                           const float* __restrict__ bias2,
                           float* __restrict__ img)
{
    __shared__ float s_w[768];
    int t = threadIdx.x;
    for (int e = t; e < 768; e += 256) s_w[e] = g_w2f[e];
    __syncthreads();
    int warp = t >> 5, lane = t & 31;
    int n = blockIdx.x * 8 + warp;
    int b = n >> 16;
    int i64 = g_flags[0];
    int pstride = g_flags[1];
    int gi = n * 9;  // k = 0
    int raw = i64 ? nbr[2 * gi] : nbr[gi];
    unsigned char pb = padb[gi * pstride];
    bool valid = (pb == 0) && ((unsigned)raw < (unsigned)N_ROWS);
    float4 xv = make_float4(0.f, 0.f, 0.f, 0.f);
    if (valid) xv = *(const float4*)(x + (size_t)raw * 128 + lane * 4);
    float p[3];
#pragma unroll
    for (int o = 0; o < 3; o++) {
        float4 wv = *(const float4*)&s_w[b * 384 + o * 128 + lane * 4];
        p[o] = xv.x * wv.x + xv.y * wv.y + xv.z * wv.z + xv.w * wv.w;
#pragma unroll
        for (int d = 16; d > 0; d >>= 1) p[o] += __shfl_xor_sync(0xffffffffu, p[o], d);
    }
    if (lane < 3) {
        float v = p[lane] + bias2[lane];
        img[(size_t)n * 3 + lane] = fminf(fmaxf(v, -256.f), 256.f);
    }
}

// ---------------- launch ----------------
extern "C" void kernel_launch(void* const* d_in, const int* in_sizes, int n_in,
                              void* d_out, int out_size) {
    const int*           nbr  = (const int*)d_in[0];
    const unsigned char* padb = (const unsigned char*)d_in[1];
    const float* ws   = (const float*)d_in[2];
    const float* cst  = (const float*)d_in[3];
    const float* a1W  = (const float*)d_in[4];
    const float* a1b  = (const float*)d_in[5];
    const float* w1   = (const float*)d_in[6];
    const float* nco  = (const float*)d_in[7];
    const float* nst  = (const float*)d_in[8];
    const float* b1   = (const float*)d_in[9];
    const float* a2W  = (const float*)d_in[10];
    const float* a2b  = (const float*)d_in[11];
    const float* w2   = (const float*)d_in[12];
    const float* b2   = (const float*)d_in[13];
    float* outx = (float*)d_out;
    float* img  = outx + (size_t)N_ROWS * 128;

    probe_kernel<<<1, 256>>>(nbr, padb);
    styles_kernel<<<256, 128>>>(ws, a1W, a1b, a2W, a2b);
    demod_kernel<<<256, 128>>>(w1);
    bmat_kernel<<<576, 256>>>(w1, w2);
    gemm_kernel<<<1024, 256>>>(nbr, padb, cst, nco, nst, b1, outx);
    img_kernel<<<16384, 256>>>(nbr, padb, outx, b2, img);
}

// round 3
// speedup vs baseline: 2.3781x; 2.3781x over previous
#include <cuda_runtime.h>
#include <cuda_bf16.h>
#include <cstdint>

#define F_FACES 65536
#define N_ROWS  131072
#define C_CH    128
#define WDIM    512
#define KNB     9
#define KTOT    1152
#define NCHUNK  36
#define NSTAGE  4

// smem layout
#define SM_SF      0            // 128*9*4 = 4608 B
#define SM_STAGES  8192
#define STAGE_SZ   32768        // A_h 8K | A_l 8K | B_h 8K | B_l 8K
#define SMEM_TOTAL (SM_STAGES + NSTAGE * STAGE_SZ)

// ---------------- device scratch ----------------
__device__ int   g_flags[2];
__device__ float g_styles[256];
__device__ float g_styles2[256];
__device__ float g_demod[256];
__device__ float g_w2f[768];
__device__ __align__(16) __nv_bfloat16 g_cst_h[F_FACES * C_CH];
__device__ __align__(16) __nv_bfloat16 g_cst_l[F_FACES * C_CH];
__device__ __align__(16) __nv_bfloat16 g_Bmat_h[2 * KTOT * C_CH];  // [b][kk][o]
__device__ __align__(16) __nv_bfloat16 g_Bmat_l[2 * KTOT * C_CH];

// ---------------- ptx helpers (baseline sm_80+ features only) ----------------
__device__ __forceinline__ uint32_t smem_u32(const void* p) {
    uint32_t a;
    asm("{ .reg .u64 t; cvta.to.shared.u64 t, %1; cvt.u32.u64 %0, t; }" : "=r"(a) : "l"(p));
    return a;
}
__device__ __forceinline__ void cpa16(uint32_t dst, const void* src, unsigned sz) {
    asm volatile("cp.async.cg.shared.global [%0], [%1], 16, %2;"
                 :: "r"(dst), "l"(src), "r"(sz) : "memory");
}
__device__ __forceinline__ void cpa_commit() {
    asm volatile("cp.async.commit_group;" ::: "memory");
}
template <int N>
__device__ __forceinline__ void cpa_wait() {
    asm volatile("cp.async.wait_group %0;" :: "n"(N) : "memory");
}
__device__ __forceinline__ void ldsm4(uint32_t* r, uint32_t addr) {
    asm volatile("ldmatrix.sync.aligned.m8n8.x4.shared.b16 {%0,%1,%2,%3}, [%4];"
                 : "=r"(r[0]), "=r"(r[1]), "=r"(r[2]), "=r"(r[3]) : "r"(addr));
}
__device__ __forceinline__ void ldsm4t(uint32_t* r, uint32_t addr) {
    asm volatile("ldmatrix.sync.aligned.m8n8.x4.trans.shared.b16 {%0,%1,%2,%3}, [%4];"
                 : "=r"(r[0]), "=r"(r[1]), "=r"(r[2]), "=r"(r[3]) : "r"(addr));
}
__device__ __forceinline__ void mma16816(float* c, const uint32_t* a, const uint32_t* b) {
    asm volatile("mma.sync.aligned.m16n8k16.row.col.f32.bf16.bf16.f32 "
                 "{%0,%1,%2,%3}, {%4,%5,%6,%7}, {%8,%9}, {%0,%1,%2,%3};"
                 : "+f"(c[0]), "+f"(c[1]), "+f"(c[2]), "+f"(c[3])
                 : "r"(a[0]), "r"(a[1]), "r"(a[2]), "r"(a[3]), "r"(b[0]), "r"(b[1]));
}
__device__ __forceinline__ void bf_split(float x, __nv_bfloat16& h, __nv_bfloat16& l) {
    h = __float2bfloat16_rn(x);
    l = __float2bfloat16_rn(x - __bfloat162float(h));
}

// ---------------- probe ----------------
__global__ void probe_kernel(const int* __restrict__ nbr,
                             const unsigned char* __restrict__ padb) {
    __shared__ int s_or[2];
    int t = threadIdx.x;
    if (t < 2) s_or[t] = 0;
    __syncthreads();
    int v = 0;
    if (t < 128) {
        for (int q = 0; q < 32; q++) { int j = t * 32 + q; v |= nbr[2 * j + 1]; }
        atomicOr(&s_or[0], v);
    } else {
        int tt = t - 128;
        for (int q = 0; q < 32; q++) { int idx = tt * 32 + q; if (idx & 3) v |= (int)padb[idx]; }
        atomicOr(&s_or[1], v);
    }
    __syncthreads();
    if (t == 0) { g_flags[0] = (s_or[0] == 0) ? 1 : 0; g_flags[1] = (s_or[1] == 0) ? 4 : 1; }
}

// ---------------- styles ----------------
__global__ void styles_kernel(const float* __restrict__ ws,
                              const float* __restrict__ A1, const float* __restrict__ b1,
                              const float* __restrict__ A2, const float* __restrict__ b2) {
    int j = blockIdx.x;
    int b = j >> 7, i = j & 127;
    int t = threadIdx.x;
    const float* w0 = ws + b * 2 * WDIM;
    const float* w1 = w0 + WDIM;
    const float* r1 = A1 + i * WDIM;
    const float* r2 = A2 + i * WDIM;
    float a1 = 0.f, a2 = 0.f;
    for (int jj = t; jj < WDIM; jj += 128) { a1 += w0[jj] * r1[jj]; a2 += w1[jj] * r2[jj]; }
    __shared__ float s1[128], s2[128];
    s1[t] = a1; s2[t] = a2;
    __syncthreads();
    for (int s = 64; s > 0; s >>= 1) {
        if (t < s) { s1[t] += s1[t + s]; s2[t] += s2[t + s]; }
        __syncthreads();
    }
    if (t == 0) {
        const float RSQ512 = 0.04419417382415922f;
        const float RSQ128 = 0.08838834764831845f;
        g_styles[j]  = s1[0] * RSQ512 + b1[i];
        g_styles2[j] = (s2[0] * RSQ512 + b2[i]) * RSQ128;
    }
}

// ---------------- demod ----------------
__global__ void demod_kernel(const float* __restrict__ w1) {
    int j = blockIdx.x;
    int b = j >> 7, o = j & 127;
    int i = threadIdx.x;
    float s = g_styles[b * 128 + i];
    const float* wp = w1 + o * KTOT + i * KNB;
    float sum = 0.f;
#pragma unroll
    for (int k = 0; k < 9; k++) { float w = wp[k] * s; sum += w * w; }
    __shared__ float sr[128];
    sr[i] = sum;
    __syncthreads();
    for (int st = 64; st > 0; st >>= 1) {
        if (i < st) sr[i] += sr[i + st];
        __syncthreads();
    }
    if (i == 0) g_demod[j] = rsqrtf(sr[0] + 1e-8f);
}

// ---------------- Bmat (bf16 hi/lo, [b][kk][o]) + w2f ----------------
__global__ void bmat_kernel(const float* __restrict__ w1, const float* __restrict__ w2) {
    int tid = blockIdx.x * blockDim.x + threadIdx.x;
    const int tot = 2 * KTOT * C_CH;
    for (int e = tid; e < tot; e += gridDim.x * blockDim.x) {
        int b  = e / (KTOT * C_CH);
        int r  = e - b * (KTOT * C_CH);
        int kk = r >> 7;          // k*128+i
        int o  = r & 127;
        int k  = kk >> 7;
        int i  = kk & 127;
        float v = w1[o * KTOT + i * KNB + k] * g_styles[b * 128 + i] * g_demod[b * 128 + o];
        __nv_bfloat16 h, l;
        bf_split(v, h, l);
        g_Bmat_h[e] = h;
        g_Bmat_l[e] = l;
    }
    if (tid < 768) {
        int b = tid / 384;
        int r = tid - b * 384;
        int o = r >> 7;
        int i = r & 127;
        g_w2f[tid] = w2[o * 128 + i] * g_styles2[b * 128 + i];
    }
}

// ---------------- split const into bf16 hi/lo ----------------
__global__ void split_const_kernel(const float* __restrict__ cst) {
    int i = blockIdx.x * blockDim.x + threadIdx.x;   // * 4 elements
    float4 v = ((const float4*)cst)[i];
    __nv_bfloat16 h[4], l[4];
    bf_split(v.x, h[0], l[0]);
    bf_split(v.y, h[1], l[1]);
    bf_split(v.z, h[2], l[2]);
    bf_split(v.w, h[3], l[3]);
    *(uint2*)(g_cst_h + 4 * (size_t)i) = *(uint2*)h;
    *(uint2*)(g_cst_l + 4 * (size_t)i) = *(uint2*)l;
}

// ---------------- chunk loader (cp.async) ----------------
__device__ __forceinline__ void load_chunk(
    int ck, uint32_t stage_base, const int* sf, int b, int t)
{
    int k = ck >> 2;
    int i0 = (ck & 3) << 5;
    uint32_t sA_h = stage_base;
    uint32_t sA_l = stage_base + 8192;
    uint32_t sB_h = stage_base + 16384;
    uint32_t sB_l = stage_base + 24576;
    const __nv_bfloat16* Bh = g_Bmat_h + (size_t)b * KTOT * C_CH;
    const __nv_bfloat16* Bl = g_Bmat_l + (size_t)b * KTOT * C_CH;
#pragma unroll
    for (int q = 0; q < 2; q++) {
        int idx = t + 256 * q;              // 0..511
        // A: m (128) x granule g (0..3 of 8 bf16)
        int m = idx >> 2, g = idx & 3;
        int f = sf[m * 9 + k];
        int fc = (f >= 0) ? f : 0;
        unsigned sz = (f >= 0) ? 16u : 0u;
        size_t so = (size_t)fc * C_CH + i0 + g * 8;
        uint32_t doff = m * 64 + (((g ^ ((m >> 1) & 3))) << 4);
        cpa16(sA_h + doff, g_cst_h + so, sz);
        cpa16(sA_l + doff, g_cst_l + so, sz);
        // B: krow (32) x granule gn (0..15)
        int kr = idx >> 4, gn = idx & 15;
        uint32_t bo = kr * 256 + (((gn ^ (kr & 7))) << 4);
        size_t bso = (size_t)(ck * 32 + kr) * C_CH + gn * 8;
        cpa16(sB_h + bo, Bh + bso, 16u);
        cpa16(sB_l + bo, Bl + bso, 16u);
    }
    cpa_commit();
}

// ---------------- bf16 mma.sync GEMM, fused epilogue ----------------
__global__ void __launch_bounds__(256, 1)
gemm_mma(const int* __restrict__ nbr,
         const unsigned char* __restrict__ padb,
         const float* __restrict__ noise_const,
         const float* __restrict__ noise_strength,
         const float* __restrict__ bias1,
         float* __restrict__ outx)
{
    extern __shared__ __align__(1024) char smem[];
    uint32_t sb = smem_u32(smem);
    int t = threadIdx.x;
    int warp = t >> 5, lane = t & 31;
    int row0 = blockIdx.x * 128;
    int b = row0 >> 16;

    // gather-index table
    int* sf = (int*)(smem + SM_SF);
    {
        int i64 = g_flags[0];
        int pstride = g_flags[1];
        for (int e = t; e < 128 * KNB; e += 256) {
            int m = e / 9, k = e - m * 9;
            int gi = (row0 + m) * 9 + k;
            int raw = i64 ? nbr[2 * gi] : nbr[gi];
            unsigned char pb = padb[gi * pstride];
            sf[e] = (pb == 0 && (unsigned)raw < (unsigned)N_ROWS) ? (raw & (F_FACES - 1)) : -1;
        }
    }
    __syncthreads();

    // prologue: stages 0..NSTAGE-2
#pragma unroll
    for (int s = 0; s < NSTAGE - 1; s++)
        load_chunk(s, sb + SM_STAGES + s * STAGE_SZ, sf, b, t);

    // warp tiling: 2 m-warps x 4 n-warps; warp tile 64(m) x 32(n)
    int wm = warp & 1, wn = warp >> 1;
    int grp = lane >> 3, lr = lane & 7;
    int mbase = wm * 64 + (grp & 1) * 8 + lr;
    int swz_a = (mbase >> 1) & 3;
    int kbase = (grp & 1) * 8 + lr;
    int gn_base = wn * 4 + (grp >> 1);    // + ng*2

    float c[4][4][4];
#pragma unroll
    for (int mt = 0; mt < 4; mt++)
#pragma unroll
        for (int nt = 0; nt < 4; nt++)
#pragma unroll
            for (int r = 0; r < 4; r++) c[mt][nt][r] = 0.f;

    for (int ck = 0; ck < NCHUNK; ck++) {
        cpa_wait<NSTAGE - 2>();
        __syncthreads();
        int nc = ck + NSTAGE - 1;
        if (nc < NCHUNK)
            load_chunk(nc, sb + SM_STAGES + (nc % NSTAGE) * STAGE_SZ, sf, b, t);
        else
            cpa_commit();   // keep group numbering uniform

        uint32_t stg = sb + SM_STAGES + (ck % NSTAGE) * STAGE_SZ;
        uint32_t aH = stg, aL = stg + 8192, bH = stg + 16384, bL = stg + 24576;

#pragma unroll
        for (int ks = 0; ks < 2; ks++) {
            uint32_t Ah[4][4], Al[4][4], Bh[2][4], Bl[2][4];
            int gk = ks * 2 + (grp >> 1);
#pragma unroll
            for (int mt = 0; mt < 4; mt++) {
                uint32_t off = (uint32_t)((mbase + mt * 16) * 64 + ((gk ^ swz_a) << 4));
                ldsm4(Ah[mt], aH + off);
                ldsm4(Al[mt], aL + off);
            }
#pragma unroll
            for (int ng = 0; ng < 2; ng++) {
                int krow = kbase + ks * 16;
                int gn = gn_base + ng * 2;
                uint32_t off = (uint32_t)(krow * 256 + ((gn ^ lr) << 4));
                ldsm4t(Bh[ng], bH + off);
                ldsm4t(Bl[ng], bL + off);
            }
#pragma unroll
            for (int mt = 0; mt < 4; mt++)
#pragma unroll
                for (int nt = 0; nt < 4; nt++) {
                    const uint32_t* bh = &Bh[nt >> 1][(nt & 1) * 2];
                    const uint32_t* bl = &Bl[nt >> 1][(nt & 1) * 2];
                    mma16816(c[mt][nt], Ah[mt], bh);
                    mma16816(c[mt][nt], Ah[mt], bl);
                    mma16816(c[mt][nt], Al[mt], bh);
                }
        }
        __syncthreads();
    }

    // epilogue: + noise + bias1, lrelu(0.2), * sqrt(2), clip +-256
    float nstr = noise_strength[0];
    const float GAIN = 1.41421356237f;
#pragma unroll
    for (int mt = 0; mt < 4; mt++) {
        int r0 = row0 + wm * 64 + mt * 16 + (lane >> 2);
        int r1 = r0 + 8;
        float nz0 = noise_const[r0 & (F_FACES - 1)] * nstr;
        float nz1 = noise_const[r1 & (F_FACES - 1)] * nstr;
#pragma unroll
        for (int nt = 0; nt < 4; nt++) {
            int n0 = wn * 32 + nt * 8 + 2 * (lane & 3);
            float b0 = bias1[n0], b1v = bias1[n0 + 1];
            float v00 = c[mt][nt][0] + nz0 + b0;
            float v01 = c[mt][nt][1] + nz0 + b1v;
            float v10 = c[mt][nt][2] + nz1 + b0;
            float v11 = c[mt][nt][3] + nz1 + b1v;
            v00 = (v00 >= 0.f) ? v00 : 0.2f * v00;
            v01 = (v01 >= 0.f) ? v01 : 0.2f * v01;
            v10 = (v10 >= 0.f) ? v10 : 0.2f * v10;
            v11 = (v11 >= 0.f) ? v11 : 0.2f * v11;
            v00 = fminf(fmaxf(v00 * GAIN, -256.f), 256.f);
            v01 = fminf(fmaxf(v01 * GAIN, -256.f), 256.f);
            v10 = fminf(fmaxf(v10 * GAIN, -256.f), 256.f);
            v11 = fminf(fmaxf(v11 * GAIN, -256.f), 256.f);
            *(float2*)(outx + (size_t)r0 * C_CH + n0) = make_float2(v00, v01);
            *(float2*)(outx + (size_t)r1 * C_CH + n0) = make_float2(v10, v11);
        }
    }
}

// ---------------- second conv (128 -> 3) ----------------
__global__ void img_kernel(const int* __restrict__ nbr,
                           const unsigned char* __restrict__ padb,
                           const float* __restrict__ x,
                           const float* __restrict__ bias2,
                           float* __restrict__ img)
{
    __shared__ float s_w[768];
    int t = threadIdx.x;
    for (int e = t; e < 768; e += 256) s_w[e] = g_w2f[e];
    __syncthreads();
    int warp = t >> 5, lane = t & 31;
    int n = blockIdx.x * 8 + warp;
    int b = n >> 16;
    int i64 = g_flags[0];
    int pstride = g_flags[1];
    int gi = n * 9;
    int raw = i64 ? nbr[2 * gi] : nbr[gi];
    unsigned char pb = padb[gi * pstride];
    bool valid = (pb == 0) && ((unsigned)raw < (unsigned)N_ROWS);
    float4 xv = make_float4(0.f, 0.f, 0.f, 0.f);
    if (valid) xv = *(const float4*)(x + (size_t)raw * 128 + lane * 4);
    float p[3];
#pragma unroll
    for (int o = 0; o < 3; o++) {
        float4 wv = *(const float4*)&s_w[b * 384 + o * 128 + lane * 4];
        p[o] = xv.x * wv.x + xv.y * wv.y + xv.z * wv.z + xv.w * wv.w;
#pragma unroll
        for (int d = 16; d > 0; d >>= 1) p[o] += __shfl_xor_sync(0xffffffffu, p[o], d);
    }
    if (lane < 3) {
        float v = p[lane] + bias2[lane];
        img[(size_t)n * 3 + lane] = fminf(fmaxf(v, -256.f), 256.f);
    }
}

// ---------------- launch ----------------
extern "C" void kernel_launch(void* const* d_in, const int* in_sizes, int n_in,
                              void* d_out, int out_size) {
    const int*           nbr  = (const int*)d_in[0];
    const unsigned char* padb = (const unsigned char*)d_in[1];
    const float* ws   = (const float*)d_in[2];
    const float* cst  = (const float*)d_in[3];
    const float* a1W  = (const float*)d_in[4];
    const float* a1b  = (const float*)d_in[5];
    const float* w1   = (const float*)d_in[6];
    const float* nco  = (const float*)d_in[7];
    const float* nst  = (const float*)d_in[8];
    const float* b1   = (const float*)d_in[9];
    const float* a2W  = (const float*)d_in[10];
    const float* a2b  = (const float*)d_in[11];
    const float* w2   = (const float*)d_in[12];
    const float* b2   = (const float*)d_in[13];
    float* outx = (float*)d_out;
    float* img  = outx + (size_t)N_ROWS * 128;

    cudaFuncSetAttribute(gemm_mma, cudaFuncAttributeMaxDynamicSharedMemorySize, SMEM_TOTAL);

    probe_kernel<<<1, 256>>>(nbr, padb);
    styles_kernel<<<256, 128>>>(ws, a1W, a1b, a2W, a2b);
    demod_kernel<<<256, 128>>>(w1);
    bmat_kernel<<<576, 256>>>(w1, w2);
    split_const_kernel<<<8192, 256>>>(cst);
    gemm_mma<<<1024, 256, SMEM_TOTAL>>>(nbr, padb, nco, nst, b1, outx);
    img_kernel<<<16384, 256>>>(nbr, padb, outx, b2, img);
}

// round 4
// speedup vs baseline: 5.1104x; 2.1489x over previous
#include <cuda_runtime.h>
#include <cuda_fp16.h>
#include <cstdint>

#define F_FACES 65536
#define N_ROWS  131072
#define C_CH    128
#define WDIM    512
#define KNB     9
#define KTOT    1152
#define NCHUNK  36
#define NSTAGE  4

// smem layout
#define SM_SF      0            // 128*9*4 = 4608 B
#define SM_STAGES  5120         // 1024-aligned
#define STAGE_SZ   16384        // A 8K | B 8K
#define SMEM_TOTAL (SM_STAGES + NSTAGE * STAGE_SZ)   // 70656 B -> 2 CTAs/SM

// ---------------- device scratch ----------------
__device__ int   g_flags[2];
__device__ float g_styles[256];
__device__ float g_styles2[256];
__device__ float g_demod[256];
__device__ float g_w2f[768];
__device__ __align__(16) __half g_cst_f16[F_FACES * C_CH];
__device__ __align__(16) __half g_Bmat_f16[2 * KTOT * C_CH];   // [b][kk][o], kk=k*128+i

// ---------------- ptx helpers (baseline sm_80+ only) ----------------
__device__ __forceinline__ uint32_t smem_u32(const void* p) {
    uint32_t a;
    asm("{ .reg .u64 t; cvta.to.shared.u64 t, %1; cvt.u32.u64 %0, t; }" : "=r"(a) : "l"(p));
    return a;
}
__device__ __forceinline__ void cpa16(uint32_t dst, const void* src, unsigned sz) {
    asm volatile("cp.async.cg.shared.global [%0], [%1], 16, %2;"
                 :: "r"(dst), "l"(src), "r"(sz) : "memory");
}
__device__ __forceinline__ void cpa_commit() {
    asm volatile("cp.async.commit_group;" ::: "memory");
}
template <int N>
__device__ __forceinline__ void cpa_wait() {
    asm volatile("cp.async.wait_group %0;" :: "n"(N) : "memory");
}
__device__ __forceinline__ void ldsm4(uint32_t* r, uint32_t addr) {
    asm volatile("ldmatrix.sync.aligned.m8n8.x4.shared.b16 {%0,%1,%2,%3}, [%4];"
                 : "=r"(r[0]), "=r"(r[1]), "=r"(r[2]), "=r"(r[3]) : "r"(addr));
}
__device__ __forceinline__ void ldsm4t(uint32_t* r, uint32_t addr) {
    asm volatile("ldmatrix.sync.aligned.m8n8.x4.trans.shared.b16 {%0,%1,%2,%3}, [%4];"
                 : "=r"(r[0]), "=r"(r[1]), "=r"(r[2]), "=r"(r[3]) : "r"(addr));
}
__device__ __forceinline__ void mma16816(float* c, const uint32_t* a, const uint32_t* b) {
    asm volatile("mma.sync.aligned.m16n8k16.row.col.f32.f16.f16.f32 "
                 "{%0,%1,%2,%3}, {%4,%5,%6,%7}, {%8,%9}, {%0,%1,%2,%3};"
                 : "+f"(c[0]), "+f"(c[1]), "+f"(c[2]), "+f"(c[3])
                 : "r"(a[0]), "r"(a[1]), "r"(a[2]), "r"(a[3]), "r"(b[0]), "r"(b[1]));
}

// ---------------- probe ----------------
__global__ void probe_kernel(const int* __restrict__ nbr,
                             const unsigned char* __restrict__ padb) {
    __shared__ int s_or[2];
    int t = threadIdx.x;
    if (t < 2) s_or[t] = 0;
    __syncthreads();
    int v = 0;
    if (t < 128) {
        for (int q = 0; q < 32; q++) { int j = t * 32 + q; v |= nbr[2 * j + 1]; }
        atomicOr(&s_or[0], v);
    } else {
        int tt = t - 128;
        for (int q = 0; q < 32; q++) { int idx = tt * 32 + q; if (idx & 3) v |= (int)padb[idx]; }
        atomicOr(&s_or[1], v);
    }
    __syncthreads();
    if (t == 0) { g_flags[0] = (s_or[0] == 0) ? 1 : 0; g_flags[1] = (s_or[1] == 0) ? 4 : 1; }
}

// ---------------- styles ----------------
__global__ void styles_kernel(const float* __restrict__ ws,
                              const float* __restrict__ A1, const float* __restrict__ b1,
                              const float* __restrict__ A2, const float* __restrict__ b2) {
    int j = blockIdx.x;
    int b = j >> 7, i = j & 127;
    int t = threadIdx.x;
    const float* w0 = ws + b * 2 * WDIM;
    const float* w1 = w0 + WDIM;
    const float* r1 = A1 + i * WDIM;
    const float* r2 = A2 + i * WDIM;
    float a1 = 0.f, a2 = 0.f;
    for (int jj = t; jj < WDIM; jj += 128) { a1 += w0[jj] * r1[jj]; a2 += w1[jj] * r2[jj]; }
    __shared__ float s1[128], s2[128];
    s1[t] = a1; s2[t] = a2;
    __syncthreads();
    for (int s = 64; s > 0; s >>= 1) {
        if (t < s) { s1[t] += s1[t + s]; s2[t] += s2[t + s]; }
        __syncthreads();
    }
    if (t == 0) {
        const float RSQ512 = 0.04419417382415922f;
        const float RSQ128 = 0.08838834764831845f;
        g_styles[j]  = s1[0] * RSQ512 + b1[i];
        g_styles2[j] = (s2[0] * RSQ512 + b2[i]) * RSQ128;
    }
}

// ---------------- demod ----------------
__global__ void demod_kernel(const float* __restrict__ w1) {
    int j = blockIdx.x;
    int b = j >> 7, o = j & 127;
    int i = threadIdx.x;
    float s = g_styles[b * 128 + i];
    const float* wp = w1 + o * KTOT + i * KNB;
    float sum = 0.f;
#pragma unroll
    for (int k = 0; k < 9; k++) { float w = wp[k] * s; sum += w * w; }
    __shared__ float sr[128];
    sr[i] = sum;
    __syncthreads();
    for (int st = 64; st > 0; st >>= 1) {
        if (i < st) sr[i] += sr[i + st];
        __syncthreads();
    }
    if (i == 0) g_demod[j] = rsqrtf(sr[0] + 1e-8f);
}

// ---------------- Bmat (fp16, [b][kk][o]) + w2f ----------------
__global__ void bmat_kernel(const float* __restrict__ w1, const float* __restrict__ w2) {
    int tid = blockIdx.x * blockDim.x + threadIdx.x;
    const int tot = 2 * KTOT * C_CH;
    for (int e = tid; e < tot; e += gridDim.x * blockDim.x) {
        int b  = e / (KTOT * C_CH);
        int r  = e - b * (KTOT * C_CH);
        int kk = r >> 7;          // k*128+i
        int o  = r & 127;
        int k  = kk >> 7;
        int i  = kk & 127;
        float v = w1[o * KTOT + i * KNB + k] * g_styles[b * 128 + i] * g_demod[b * 128 + o];
        g_Bmat_f16[e] = __float2half_rn(v);
    }
    if (tid < 768) {
        int b = tid / 384;
        int r = tid - b * 384;
        int o = r >> 7;
        int i = r & 127;
        g_w2f[tid] = w2[o * 128 + i] * g_styles2[b * 128 + i];
    }
}

// ---------------- convert const to fp16 ----------------
__global__ void split_const_kernel(const float* __restrict__ cst) {
    int i = blockIdx.x * blockDim.x + threadIdx.x;   // *4 elements
    float4 v = ((const float4*)cst)[i];
    __half h[4];
    h[0] = __float2half_rn(v.x);
    h[1] = __float2half_rn(v.y);
    h[2] = __float2half_rn(v.z);
    h[3] = __float2half_rn(v.w);
    *(uint2*)(g_cst_f16 + 4 * (size_t)i) = *(uint2*)h;
}

// ---------------- chunk loader (cp.async) ----------------
__device__ __forceinline__ void load_chunk(
    int ck, uint32_t stage_base, const int* sf, int b, int t)
{
    int k = ck >> 2;
    int i0 = (ck & 3) << 5;
    uint32_t sA = stage_base;
    uint32_t sB = stage_base + 8192;
    const __half* Bp = g_Bmat_f16 + (size_t)b * KTOT * C_CH;
#pragma unroll
    for (int q = 0; q < 2; q++) {
        int v = t + 256 * q;                // 0..511
        // A: m (128) x granule g (0..3 of 8 fp16)
        int m = v >> 2, g = v & 3;
        int f = sf[m * 9 + k];
        int fc = (f >= 0) ? f : 0;
        unsigned sz = (f >= 0) ? 16u : 0u;
        size_t so = (size_t)fc * C_CH + i0 + g * 8;
        uint32_t doff = m * 64 + (((g ^ ((m >> 1) & 3))) << 4);
        cpa16(sA + doff, g_cst_f16 + so, sz);
        // B: krow (32) x granule gn (0..15)
        int kr = v >> 4, gn = v & 15;
        uint32_t bo = kr * 256 + (((gn ^ (kr & 7))) << 4);
        size_t bso = (size_t)(ck * 32 + kr) * C_CH + gn * 8;
        cpa16(sB + bo, Bp + bso, 16u);
    }
    cpa_commit();
}

// ---------------- fp16 mma.sync GEMM, fused epilogue ----------------
__global__ void __launch_bounds__(256, 2)
gemm_mma(const int* __restrict__ nbr,
         const unsigned char* __restrict__ padb,
         const float* __restrict__ noise_const,
         const float* __restrict__ noise_strength,
         const float* __restrict__ bias1,
         float* __restrict__ outx)
{
    extern __shared__ __align__(1024) char smem[];
    uint32_t sb = smem_u32(smem);
    int t = threadIdx.x;
    int warp = t >> 5, lane = t & 31;
    int row0 = blockIdx.x * 128;
    int b = row0 >> 16;

    // gather-index table
    int* sf = (int*)(smem + SM_SF);
    {
        int i64 = g_flags[0];
        int pstride = g_flags[1];
        for (int e = t; e < 128 * KNB; e += 256) {
            int m = e / 9, k = e - m * 9;
            int gi = (row0 + m) * 9 + k;
            int raw = i64 ? nbr[2 * gi] : nbr[gi];
            unsigned char pb = padb[gi * pstride];
            sf[e] = (pb == 0 && (unsigned)raw < (unsigned)N_ROWS) ? (raw & (F_FACES - 1)) : -1;
        }
    }
    __syncthreads();

    // prologue: stages 0..NSTAGE-2
#pragma unroll
    for (int s = 0; s < NSTAGE - 1; s++)
        load_chunk(s, sb + SM_STAGES + s * STAGE_SZ, sf, b, t);

    // warp tiling: 2 m-warps x 4 n-warps; warp tile 64(m) x 32(n)
    int wm = warp & 1, wn = warp >> 1;
    int grp = lane >> 3, lr = lane & 7;
    int mbase = wm * 64 + (grp & 1) * 8 + lr;
    int swz_a = (mbase >> 1) & 3;
    int kbase = (grp & 1) * 8 + lr;
    int gn_base = wn * 4 + (grp >> 1);

    float c[4][4][4];
#pragma unroll
    for (int mt = 0; mt < 4; mt++)
#pragma unroll
        for (int nt = 0; nt < 4; nt++)
#pragma unroll
            for (int r = 0; r < 4; r++) c[mt][nt][r] = 0.f;

    for (int ck = 0; ck < NCHUNK; ck++) {
        cpa_wait<NSTAGE - 2>();
        __syncthreads();
        int nc = ck + NSTAGE - 1;
        if (nc < NCHUNK)
            load_chunk(nc, sb + SM_STAGES + (nc % NSTAGE) * STAGE_SZ, sf, b, t);
        else
            cpa_commit();

        uint32_t stg = sb + SM_STAGES + (ck % NSTAGE) * STAGE_SZ;
        uint32_t aP = stg, bP = stg + 8192;

#pragma unroll
        for (int ks = 0; ks < 2; ks++) {
            uint32_t Af[4][4], Bf[2][4];
            int gk = ks * 2 + (grp >> 1);
#pragma unroll
            for (int mt = 0; mt < 4; mt++) {
                uint32_t off = (uint32_t)((mbase + mt * 16) * 64 + ((gk ^ swz_a) << 4));
                ldsm4(Af[mt], aP + off);
            }
#pragma unroll
            for (int ng = 0; ng < 2; ng++) {
                int krow = kbase + ks * 16;
                int gn = gn_base + ng * 2;
                uint32_t off = (uint32_t)(krow * 256 + ((gn ^ lr) << 4));
                ldsm4t(Bf[ng], bP + off);
            }
#pragma unroll
            for (int mt = 0; mt < 4; mt++)
#pragma unroll
                for (int nt = 0; nt < 4; nt++)
                    mma16816(c[mt][nt], Af[mt], &Bf[nt >> 1][(nt & 1) * 2]);
        }
        __syncthreads();
    }

    // epilogue: + noise + bias1, lrelu(0.2), * sqrt(2), clip +-256
    float nstr = noise_strength[0];
    const float GAIN = 1.41421356237f;
#pragma unroll
    for (int mt = 0; mt < 4; mt++) {
        int r0 = row0 + wm * 64 + mt * 16 + (lane >> 2);
        int r1 = r0 + 8;
        float nz0 = noise_const[r0 & (F_FACES - 1)] * nstr;
        float nz1 = noise_const[r1 & (F_FACES - 1)] * nstr;
#pragma unroll
        for (int nt = 0; nt < 4; nt++) {
            int n0 = wn * 32 + nt * 8 + 2 * (lane & 3);
            float b0 = bias1[n0], b1v = bias1[n0 + 1];
            float v00 = c[mt][nt][0] + nz0 + b0;
            float v01 = c[mt][nt][1] + nz0 + b1v;
            float v10 = c[mt][nt][2] + nz1 + b0;
            float v11 = c[mt][nt][3] + nz1 + b1v;
            v00 = (v00 >= 0.f) ? v00 : 0.2f * v00;
            v01 = (v01 >= 0.f) ? v01 : 0.2f * v01;
            v10 = (v10 >= 0.f) ? v10 : 0.2f * v10;
            v11 = (v11 >= 0.f) ? v11 : 0.2f * v11;
            v00 = fminf(fmaxf(v00 * GAIN, -256.f), 256.f);
            v01 = fminf(fmaxf(v01 * GAIN, -256.f), 256.f);
            v10 = fminf(fmaxf(v10 * GAIN, -256.f), 256.f);
            v11 = fminf(fmaxf(v11 * GAIN, -256.f), 256.f);
            *(float2*)(outx + (size_t)r0 * C_CH + n0) = make_float2(v00, v01);
            *(float2*)(outx + (size_t)r1 * C_CH + n0) = make_float2(v10, v11);
        }
    }
}

// ---------------- second conv (128 -> 3) ----------------
__global__ void img_kernel(const int* __restrict__ nbr,
                           const unsigned char* __restrict__ padb,
                           const float* __restrict__ x,
                           const float* __restrict__ bias2,
                           float* __restrict__ img)
{
    __shared__ float s_w[768];
    int t = threadIdx.x;
    for (int e = t; e < 768; e += 256) s_w[e] = g_w2f[e];
    __syncthreads();
    int warp = t >> 5, lane = t & 31;
    int n = blockIdx.x * 8 + warp;
    int b = n >> 16;
    int i64 = g_flags[0];
    int pstride = g_flags[1];
    int gi = n * 9;
    int raw = i64 ? nbr[2 * gi] : nbr[gi];
    unsigned char pb = padb[gi * pstride];
    bool valid = (pb == 0) && ((unsigned)raw < (unsigned)N_ROWS);
    float4 xv = make_float4(0.f, 0.f, 0.f, 0.f);
    if (valid) xv = *(const float4*)(x + (size_t)raw * 128 + lane * 4);
    float p[3];
#pragma unroll
    for (int o = 0; o < 3; o++) {
        float4 wv = *(const float4*)&s_w[b * 384 + o * 128 + lane * 4];
        p[o] = xv.x * wv.x + xv.y * wv.y + xv.z * wv.z + xv.w * wv.w;
#pragma unroll
        for (int d = 16; d > 0; d >>= 1) p[o] += __shfl_xor_sync(0xffffffffu, p[o], d);
    }
    if (lane < 3) {
        float v = p[lane] + bias2[lane];
        img[(size_t)n * 3 + lane] = fminf(fmaxf(v, -256.f), 256.f);
    }
}

// ---------------- launch ----------------
extern "C" void kernel_launch(void* const* d_in, const int* in_sizes, int n_in,
                              void* d_out, int out_size) {
    const int*           nbr  = (const int*)d_in[0];
    const unsigned char* padb = (const unsigned char*)d_in[1];
    const float* ws   = (const float*)d_in[2];
    const float* cst  = (const float*)d_in[3];
    const float* a1W  = (const float*)d_in[4];
    const float* a1b  = (const float*)d_in[5];
    const float* w1   = (const float*)d_in[6];
    const float* nco  = (const float*)d_in[7];
    const float* nst  = (const float*)d_in[8];
    const float* b1   = (const float*)d_in[9];
    const float* a2W  = (const float*)d_in[10];
    const float* a2b  = (const float*)d_in[11];
    const float* w2   = (const float*)d_in[12];
    const float* b2   = (const float*)d_in[13];
    float* outx = (float*)d_out;
    float* img  = outx + (size_t)N_ROWS * 128;

    cudaFuncSetAttribute(gemm_mma, cudaFuncAttributeMaxDynamicSharedMemorySize, SMEM_TOTAL);

    probe_kernel<<<1, 256>>>(nbr, padb);
    styles_kernel<<<256, 128>>>(ws, a1W, a1b, a2W, a2b);
    demod_kernel<<<256, 128>>>(w1);
    bmat_kernel<<<576, 256>>>(w1, w2);
    split_const_kernel<<<8192, 256>>>(cst);
    gemm_mma<<<1024, 256, SMEM_TOTAL>>>(nbr, padb, nco, nst, b1, outx);
    img_kernel<<<16384, 256>>>(nbr, padb, outx, b2, img);
}

// round 5
// speedup vs baseline: 5.3518x; 1.0472x over previous
#include <cuda_runtime.h>
#include <cuda_fp16.h>
#include <cstdint>

#define F_FACES 65536
#define N_ROWS  131072
#define C_CH    128
#define WDIM    512
#define KNB     9
#define KTOT    1152
#define NCHUNK  18
#define NSTAGE  3

// smem layout
#define SM_SF      0            // 128*9*4 = 4608 B
#define SM_STAGES  5120         // 1024-aligned
#define STAGE_SZ   32768        // A 16K | B 16K
#define SMEM_TOTAL (SM_STAGES + NSTAGE * STAGE_SZ)   // 103424 B -> 2 CTAs/SM

// ---------------- device scratch ----------------
__device__ int   g_flags[2];
__device__ float g_styles[256];
__device__ float g_styles2[256];
__device__ float g_w2f[768];
__device__ __align__(16) __half g_cst_f16[F_FACES * C_CH];
__device__ __align__(16) __half g_Bmat_f16[2 * KTOT * C_CH];   // [b][kk][o], kk=k*128+i

// ---------------- ptx helpers (baseline sm_80+ only) ----------------
__device__ __forceinline__ uint32_t smem_u32(const void* p) {
    uint32_t a;
    asm("{ .reg .u64 t; cvta.to.shared.u64 t, %1; cvt.u32.u64 %0, t; }" : "=r"(a) : "l"(p));
    return a;
}
__device__ __forceinline__ void cpa16(uint32_t dst, const void* src, unsigned sz) {
    asm volatile("cp.async.cg.shared.global [%0], [%1], 16, %2;"
                 :: "r"(dst), "l"(src), "r"(sz) : "memory");
}
__device__ __forceinline__ void cpa_commit() {
    asm volatile("cp.async.commit_group;" ::: "memory");
}
template <int N>
__device__ __forceinline__ void cpa_wait() {
    asm volatile("cp.async.wait_group %0;" :: "n"(N) : "memory");
}
__device__ __forceinline__ void ldsm4(uint32_t* r, uint32_t addr) {
    asm volatile("ldmatrix.sync.aligned.m8n8.x4.shared.b16 {%0,%1,%2,%3}, [%4];"
                 : "=r"(r[0]), "=r"(r[1]), "=r"(r[2]), "=r"(r[3]) : "r"(addr));
}
__device__ __forceinline__ void ldsm4t(uint32_t* r, uint32_t addr) {
    asm volatile("ldmatrix.sync.aligned.m8n8.x4.trans.shared.b16 {%0,%1,%2,%3}, [%4];"
                 : "=r"(r[0]), "=r"(r[1]), "=r"(r[2]), "=r"(r[3]) : "r"(addr));
}
__device__ __forceinline__ void mma16816(float* c, const uint32_t* a, const uint32_t* b) {
    asm volatile("mma.sync.aligned.m16n8k16.row.col.f32.f16.f16.f32 "
                 "{%0,%1,%2,%3}, {%4,%5,%6,%7}, {%8,%9}, {%0,%1,%2,%3};"
                 : "+f"(c[0]), "+f"(c[1]), "+f"(c[2]), "+f"(c[3])
                 : "r"(a[0]), "r"(a[1]), "r"(a[2]), "r"(a[3]), "r"(b[0]), "r"(b[1]));
}

// ---------------- styles (blocks 0..255) + probe (block 256) ----------------
__global__ void styles_probe_kernel(const float* __restrict__ ws,
                                    const float* __restrict__ A1, const float* __restrict__ b1,
                                    const float* __restrict__ A2, const float* __restrict__ b2,
                                    const int* __restrict__ nbr,
                                    const unsigned char* __restrict__ padb) {
    int t = threadIdx.x;
    if (blockIdx.x == 256) {
        __shared__ int s_or[2];
        if (t < 2) s_or[t] = 0;
        __syncthreads();
        int v = 0;
        if (t < 64) {
            for (int q = 0; q < 64; q++) { int j = t * 64 + q; v |= nbr[2 * j + 1]; }
            atomicOr(&s_or[0], v);
        } else {
            int tt = t - 64;
            for (int q = 0; q < 64; q++) { int idx = tt * 64 + q; if (idx & 3) v |= (int)padb[idx]; }
            atomicOr(&s_or[1], v);
        }
        __syncthreads();
        if (t == 0) { g_flags[0] = (s_or[0] == 0) ? 1 : 0; g_flags[1] = (s_or[1] == 0) ? 4 : 1; }
        return;
    }
    int j = blockIdx.x;
    int b = j >> 7, i = j & 127;
    const float* w0 = ws + b * 2 * WDIM;
    const float* w1 = w0 + WDIM;
    const float* r1 = A1 + i * WDIM;
    const float* r2 = A2 + i * WDIM;
    float a1 = 0.f, a2 = 0.f;
    for (int jj = t; jj < WDIM; jj += 128) { a1 += w0[jj] * r1[jj]; a2 += w1[jj] * r2[jj]; }
    __shared__ float s1[128], s2[128];
    s1[t] = a1; s2[t] = a2;
    __syncthreads();
    for (int s = 64; s > 0; s >>= 1) {
        if (t < s) { s1[t] += s1[t + s]; s2[t] += s2[t + s]; }
        __syncthreads();
    }
    if (t == 0) {
        const float RSQ512 = 0.04419417382415922f;
        const float RSQ128 = 0.08838834764831845f;
        g_styles[j]  = s1[0] * RSQ512 + b1[i];
        g_styles2[j] = (s2[0] * RSQ512 + b2[i]) * RSQ128;
    }
}

// ---------------- demod + Bmat (fp16, [b][kk][o]) + w2f, one block per (b,o) ----------------
__global__ void demod_bmat_kernel(const float* __restrict__ w1, const float* __restrict__ w2) {
    int j = blockIdx.x;
    int b = j >> 7, o = j & 127;
    int i = threadIdx.x;
    float s = g_styles[b * 128 + i];
    const float* wp = w1 + o * KTOT + i * KNB;
    float wv[KNB];
    float sum = 0.f;
#pragma unroll
    for (int k = 0; k < KNB; k++) { wv[k] = wp[k] * s; sum += wv[k] * wv[k]; }
    __shared__ float sr[128];
    sr[i] = sum;
    __syncthreads();
    for (int st = 64; st > 0; st >>= 1) {
        if (i < st) sr[i] += sr[i + st];
        __syncthreads();
    }
    __shared__ float s_d;
    if (i == 0) s_d = rsqrtf(sr[0] + 1e-8f);
    __syncthreads();
    float d = s_d;
    __half* Bp = g_Bmat_f16 + ((size_t)b * KTOT) * C_CH + o;
#pragma unroll
    for (int k = 0; k < KNB; k++)
        Bp[(size_t)(k * 128 + i) * C_CH] = __float2half_rn(wv[k] * d);
    if (o < 3)
        g_w2f[b * 384 + o * 128 + i] = w2[o * 128 + i] * g_styles2[b * 128 + i];
}

// ---------------- convert const to fp16 ----------------
__global__ void split_const_kernel(const float* __restrict__ cst) {
    int i = blockIdx.x * blockDim.x + threadIdx.x;   // *4 elements
    float4 v = ((const float4*)cst)[i];
    __half h[4];
    h[0] = __float2half_rn(v.x);
    h[1] = __float2half_rn(v.y);
    h[2] = __float2half_rn(v.z);
    h[3] = __float2half_rn(v.w);
    *(uint2*)(g_cst_f16 + 4 * (size_t)i) = *(uint2*)h;
}

// ---------------- chunk loader (cp.async), BK=64 ----------------
__device__ __forceinline__ void load_chunk(
    int ck, uint32_t stage_base, const int* sf, int b, int t)
{
    int k = ck >> 1;
    int i0 = (ck & 1) << 6;
    uint32_t sA = stage_base;
    uint32_t sB = stage_base + 16384;
    const __half* Bp = g_Bmat_f16 + (size_t)b * KTOT * C_CH;
#pragma unroll
    for (int q = 0; q < 4; q++) {
        int v = t + 256 * q;                // 0..1023
        // A: m (128 rows) x granule g (0..7, 8 fp16 each); row stride 128B
        int m = v >> 3, g = v & 7;
        int f = sf[m * 9 + k];
        int fc = (f >= 0) ? f : 0;
        unsigned sz = (f >= 0) ? 16u : 0u;
        size_t so = (size_t)fc * C_CH + i0 + g * 8;
        uint32_t doff = m * 128 + (((g ^ (m & 7))) << 4);
        cpa16(sA + doff, g_cst_f16 + so, sz);
        // B: krow (64) x granule gn (0..15); row stride 256B
        int kr = v >> 4, gn = v & 15;
        uint32_t bo = kr * 256 + (((gn ^ (kr & 7))) << 4);
        size_t bso = (size_t)(ck * 64 + kr) * C_CH + gn * 8;
        cpa16(sB + bo, Bp + bso, 16u);
    }
    cpa_commit();
}

// ---------------- fp16 mma.sync GEMM, fused epilogue ----------------
__global__ void __launch_bounds__(256, 2)
gemm_mma(const int* __restrict__ nbr,
         const unsigned char* __restrict__ padb,
         const float* __restrict__ noise_const,
         const float* __restrict__ noise_strength,
         const float* __restrict__ bias1,
         float* __restrict__ outx)
{
    extern __shared__ __align__(1024) char smem[];
    uint32_t sb = smem_u32(smem);
    int t = threadIdx.x;
    int warp = t >> 5, lane = t & 31;
    int row0 = blockIdx.x * 128;
    int b = row0 >> 16;

    // gather-index table
    int* sf = (int*)(smem + SM_SF);
    {
        int i64 = g_flags[0];
        int pstride = g_flags[1];
        for (int e = t; e < 128 * KNB; e += 256) {
            int m = e / 9, k = e - m * 9;
            int gi = (row0 + m) * 9 + k;
            int raw = i64 ? nbr[2 * gi] : nbr[gi];
            unsigned char pb = padb[gi * pstride];
            sf[e] = (pb == 0 && (unsigned)raw < (unsigned)N_ROWS) ? (raw & (F_FACES - 1)) : -1;
        }
    }
    __syncthreads();

    // prologue: stages 0..NSTAGE-2
#pragma unroll
    for (int s = 0; s < NSTAGE - 1; s++)
        load_chunk(s, sb + SM_STAGES + s * STAGE_SZ, sf, b, t);

    // warp tiling: 2 m-warps x 4 n-warps; warp tile 64(m) x 32(n)
    int wm = warp & 1, wn = warp >> 1;
    int grp = lane >> 3, lr = lane & 7;
    int mbase = wm * 64 + (grp & 1) * 8 + lr;
    int swz_a = mbase & 7;
    int kbase = (grp & 1) * 8 + lr;
    int gn_base = wn * 4 + (grp >> 1);

    float c[4][4][4];
#pragma unroll
    for (int mt = 0; mt < 4; mt++)
#pragma unroll
        for (int nt = 0; nt < 4; nt++)
#pragma unroll
            for (int r = 0; r < 4; r++) c[mt][nt][r] = 0.f;

    for (int ck = 0; ck < NCHUNK; ck++) {
        cpa_wait<NSTAGE - 2>();
        __syncthreads();
        int nc = ck + NSTAGE - 1;
        if (nc < NCHUNK)
            load_chunk(nc, sb + SM_STAGES + (nc % NSTAGE) * STAGE_SZ, sf, b, t);
        else
            cpa_commit();

        uint32_t stg = sb + SM_STAGES + (ck % NSTAGE) * STAGE_SZ;
        uint32_t aP = stg, bP = stg + 16384;

#pragma unroll
        for (int ks = 0; ks < 4; ks++) {
            uint32_t Af[4][4], Bf[2][4];
            int gk = ks * 2 + (grp >> 1);
#pragma unroll
            for (int mt = 0; mt < 4; mt++) {
                uint32_t off = (uint32_t)((mbase + mt * 16) * 128 + ((gk ^ swz_a) << 4));
                ldsm4(Af[mt], aP + off);
            }
#pragma unroll
            for (int ng = 0; ng < 2; ng++) {
                int krow = kbase + ks * 16;
                int gn = gn_base + ng * 2;
                uint32_t off = (uint32_t)(krow * 256 + ((gn ^ lr) << 4));
                ldsm4t(Bf[ng], bP + off);
            }
#pragma unroll
            for (int mt = 0; mt < 4; mt++)
#pragma unroll
                for (int nt = 0; nt < 4; nt++)
                    mma16816(c[mt][nt], Af[mt], &Bf[nt >> 1][(nt & 1) * 2]);
        }
        __syncthreads();
    }

    // epilogue: + noise + bias1, lrelu(0.2), * sqrt(2), clip +-256
    float nstr = noise_strength[0];
    const float GAIN = 1.41421356237f;
#pragma unroll
    for (int mt = 0; mt < 4; mt++) {
        int r0 = row0 + wm * 64 + mt * 16 + (lane >> 2);
        int r1 = r0 + 8;
        float nz0 = noise_const[r0 & (F_FACES - 1)] * nstr;
        float nz1 = noise_const[r1 & (F_FACES - 1)] * nstr;
#pragma unroll
        for (int nt = 0; nt < 4; nt++) {
            int n0 = wn * 32 + nt * 8 + 2 * (lane & 3);
            float b0 = bias1[n0], b1v = bias1[n0 + 1];
            float v00 = c[mt][nt][0] + nz0 + b0;
            float v01 = c[mt][nt][1] + nz0 + b1v;
            float v10 = c[mt][nt][2] + nz1 + b0;
            float v11 = c[mt][nt][3] + nz1 + b1v;
            v00 = (v00 >= 0.f) ? v00 : 0.2f * v00;
            v01 = (v01 >= 0.f) ? v01 : 0.2f * v01;
            v10 = (v10 >= 0.f) ? v10 : 0.2f * v10;
            v11 = (v11 >= 0.f) ? v11 : 0.2f * v11;
            v00 = fminf(fmaxf(v00 * GAIN, -256.f), 256.f);
            v01 = fminf(fmaxf(v01 * GAIN, -256.f), 256.f);
            v10 = fminf(fmaxf(v10 * GAIN, -256.f), 256.f);
            v11 = fminf(fmaxf(v11 * GAIN, -256.f), 256.f);
            *(float2*)(outx + (size_t)r0 * C_CH + n0) = make_float2(v00, v01);
            *(float2*)(outx + (size_t)r1 * C_CH + n0) = make_float2(v10, v11);
        }
    }
}

// ---------------- second conv (128 -> 3) ----------------
__global__ void img_kernel(const int* __restrict__ nbr,
                           const unsigned char* __restrict__ padb,
                           const float* __restrict__ x,
                           const float* __restrict__ bias2,
                           float* __restrict__ img)
{
    __shared__ float s_w[768];
    int t = threadIdx.x;
    for (int e = t; e < 768; e += 256) s_w[e] = g_w2f[e];
    __syncthreads();
    int warp = t >> 5, lane = t & 31;
    int n = blockIdx.x * 8 + warp;
    int b = n >> 16;
    int i64 = g_flags[0];
    int pstride = g_flags[1];
    int gi = n * 9;
    int raw = i64 ? nbr[2 * gi] : nbr[gi];
    unsigned char pb = padb[gi * pstride];
    bool valid = (pb == 0) && ((unsigned)raw < (unsigned)N_ROWS);
    float4 xv = make_float4(0.f, 0.f, 0.f, 0.f);
    if (valid) xv = *(const float4*)(x + (size_t)raw * 128 + lane * 4);
    float p[3];
#pragma unroll
    for (int o = 0; o < 3; o++) {
        float4 wv = *(const float4*)&s_w[b * 384 + o * 128 + lane * 4];
        p[o] = xv.x * wv.x + xv.y * wv.y + xv.z * wv.z + xv.w * wv.w;
#pragma unroll
        for (int d = 16; d > 0; d >>= 1) p[o] += __shfl_xor_sync(0xffffffffu, p[o], d);
    }
    if (lane < 3) {
        float v = p[lane] + bias2[lane];
        img[(size_t)n * 3 + lane] = fminf(fmaxf(v, -256.f), 256.f);
    }
}

// ---------------- launch ----------------
extern "C" void kernel_launch(void* const* d_in, const int* in_sizes, int n_in,
                              void* d_out, int out_size) {
    const int*           nbr  = (const int*)d_in[0];
    const unsigned char* padb = (const unsigned char*)d_in[1];
    const float* ws   = (const float*)d_in[2];
    const float* cst  = (const float*)d_in[3];
    const float* a1W  = (const float*)d_in[4];
    const float* a1b  = (const float*)d_in[5];
    const float* w1   = (const float*)d_in[6];
    const float* nco  = (const float*)d_in[7];
    const float* nst  = (const float*)d_in[8];
    const float* b1   = (const float*)d_in[9];
    const float* a2W  = (const float*)d_in[10];
    const float* a2b  = (const float*)d_in[11];
    const float* w2   = (const float*)d_in[12];
    const float* b2   = (const float*)d_in[13];
    float* outx = (float*)d_out;
    float* img  = outx + (size_t)N_ROWS * 128;

    static cudaStream_t side = nullptr;
    static cudaEvent_t ev_fork = nullptr, ev_join = nullptr;
    static int inited = 0;
    if (!inited) {
        cudaFuncSetAttribute(gemm_mma, cudaFuncAttributeMaxDynamicSharedMemorySize, SMEM_TOTAL);
        cudaStreamCreateWithFlags(&side, cudaStreamNonBlocking);
        cudaEventCreateWithFlags(&ev_fork, cudaEventDisableTiming);
        cudaEventCreateWithFlags(&ev_join, cudaEventDisableTiming);
        inited = 1;
    }

    // fork: const fp32->fp16 conversion overlaps the style/weight prep chain
    cudaEventRecord(ev_fork, 0);
    cudaStreamWaitEvent(side, ev_fork, 0);
    split_const_kernel<<<8192, 256, 0, side>>>(cst);
    cudaEventRecord(ev_join, side);

    styles_probe_kernel<<<257, 128>>>(ws, a1W, a1b, a2W, a2b, nbr, padb);
    demod_bmat_kernel<<<256, 128>>>(w1, w2);

    cudaStreamWaitEvent(0, ev_join, 0);
    gemm_mma<<<1024, 256, SMEM_TOTAL>>>(nbr, padb, nco, nst, b1, outx);
    img_kernel<<<16384, 256>>>(nbr, padb, outx, b2, img);
}